// round 1
// baseline (speedup 1.0000x reference)
#include <cuda_runtime.h>
#include <cuda_bf16.h>

// Problem constants
#define Bn   64
#define Tn   128
#define Fn   128
#define Hn   128
#define LATn 512
#define UNF  6

// ---------------------------------------------------------------------------
// Device scratch (no allocations allowed)
// ---------------------------------------------------------------------------
__device__ float g_NS[Tn * Bn * Hn];          // sensory numerator  [t][b][j]
__device__ float g_DS[Tn * Bn * Hn];          // sensory denominator
__device__ float g_h0[Tn * Bn * Hn];          // layer-0 hidden seq
__device__ float g_h1[Tn * Bn * Hn];          // layer-1 hidden seq
__device__ float g_part[8 * 2 * Bn * LATn];   // head GEMM k-split partials

// ---------------------------------------------------------------------------
// Sensory precompute: NS/DS[t,b,j] = const + sum_i C_ij * tanh(u_i*hs - hm)
// grid 512 blocks x 128 threads; each block: 16 (t,b) pairs, params in SMEM.
// ---------------------------------------------------------------------------
__global__ __launch_bounds__(128, 1)
void sensory_kernel(const float* __restrict__ U, int stride_t, int stride_b,
                    const float* __restrict__ ssig, const float* __restrict__ smu,
                    const float* __restrict__ sw,   const float* __restrict__ sev,
                    float* __restrict__ NS, float* __restrict__ DS)
{
    extern __shared__ float sm[];
    float* sHs = sm;                  // 16384
    float* sNh = sm + 16384;          // 16384
    float* sCc = sm + 32768;          // 16384
    float* su  = sm + 49152;          // 16*128

    const int j     = threadIdx.x;
    const int pair0 = blockIdx.x * 16;

    float cC = 0.f, cA = 0.f;
    for (int i = 0; i < Hn; ++i) {
        int idx = i * Hn + j;
        float sg = ssig[idx];
        float m  = smu[idx];
        sHs[idx] = 0.5f * sg;
        sNh[idx] = -0.5f * sg * m;
        float ww = sw[idx];
        float c  = 0.5f * ww * sev[idx];
        sCc[idx] = c;
        cC += c;
        cA += 0.5f * ww;
    }
    for (int p = 0; p < 16; ++p) {
        int pr = pair0 + p;
        int t  = pr >> 6;      // pr / Bn
        int b  = pr & 63;
        su[p * Hn + j] = U[t * stride_t + b * stride_b + j];
    }
    __syncthreads();

    for (int pg = 0; pg < 4; ++pg) {
        const float* u0 = su + (pg * 4 + 0) * Hn;
        const float* u1 = su + (pg * 4 + 1) * Hn;
        const float* u2 = su + (pg * 4 + 2) * Hn;
        const float* u3 = su + (pg * 4 + 3) * Hn;
        float n0 = cC, n1 = cC, n2 = cC, n3 = cC;
        float d0 = cA, d1 = cA, d2 = cA, d3 = cA;
        #pragma unroll 4
        for (int i = 0; i < Hn; ++i) {
            int idx = i * Hn + j;
            float hs = sHs[idx];
            float nh = sNh[idx];
            float c  = sCc[idx];
            float ac = fabsf(c);
            float t0, t1, t2, t3;
            float a0 = fmaf(u0[i], hs, nh);
            float a1 = fmaf(u1[i], hs, nh);
            float a2 = fmaf(u2[i], hs, nh);
            float a3 = fmaf(u3[i], hs, nh);
            asm("tanh.approx.f32 %0, %1;" : "=f"(t0) : "f"(a0));
            asm("tanh.approx.f32 %0, %1;" : "=f"(t1) : "f"(a1));
            asm("tanh.approx.f32 %0, %1;" : "=f"(t2) : "f"(a2));
            asm("tanh.approx.f32 %0, %1;" : "=f"(t3) : "f"(a3));
            n0 = fmaf(c, t0, n0);  d0 = fmaf(ac, t0, d0);
            n1 = fmaf(c, t1, n1);  d1 = fmaf(ac, t1, d1);
            n2 = fmaf(c, t2, n2);  d2 = fmaf(ac, t2, d2);
            n3 = fmaf(c, t3, n3);  d3 = fmaf(ac, t3, d3);
        }
        int o = (pair0 + pg * 4) * Hn + j;
        NS[o]          = n0;  DS[o]          = d0;
        NS[o + Hn]     = n1;  DS[o + Hn]     = d1;
        NS[o + 2 * Hn] = n2;  DS[o + 2 * Hn] = d2;
        NS[o + 3 * Hn] = n3;  DS[o + 3 * Hn] = d3;
    }
}

// ---------------------------------------------------------------------------
// LTC recurrent layer. grid = Bn blocks (one batch each), 512 threads:
// thread (j = tid&127, k = tid>>7) owns i in [32k, 32k+32).
// hsig/nhm in registers, C in SMEM, v broadcast via SMEM, 2 barriers/unfold.
// ---------------------------------------------------------------------------
__global__ __launch_bounds__(512, 1)
void ltc_kernel(const float* __restrict__ sigma, const float* __restrict__ mu,
                const float* __restrict__ w,     const float* __restrict__ erev,
                const float* __restrict__ gleak, const float* __restrict__ vleak,
                const float* __restrict__ cmv,
                const float* __restrict__ NS,    const float* __restrict__ DS,
                float* __restrict__ out)
{
    extern __shared__ float sm[];
    float* sC     = sm;            // 16384
    float* sv     = sm + 16384;    // 128
    float* redN   = sm + 16512;    // 512
    float* redD   = sm + 17024;    // 512
    float* sBaseN = sm + 17536;    // 128
    float* sBaseD = sm + 17664;    // 128
    float* sCmt   = sm + 17792;    // 128

    const int b   = blockIdx.x;
    const int tid = threadIdx.x;
    const int j   = tid & 127;
    const int k   = tid >> 7;

    float hsig[32], nhm[32];
    float cpart = 0.f, apart = 0.f;
    #pragma unroll
    for (int s = 0; s < 32; ++s) {
        int i = k * 32 + s;
        int idx = i * Hn + j;
        float sg = sigma[idx];
        float m  = mu[idx];
        hsig[s] = 0.5f * sg;
        nhm[s]  = -0.5f * sg * m;
        float ww = w[idx];
        float c  = 0.5f * ww * erev[idx];
        sC[idx] = c;
        cpart += c;
        apart += 0.5f * ww;
    }
    redN[k * Hn + j] = cpart;
    redD[k * Hn + j] = apart;
    if (tid < Hn) sv[tid] = 0.f;
    __syncthreads();
    if (k == 0) {
        float cC = redN[j] + redN[Hn + j] + redN[2 * Hn + j] + redN[3 * Hn + j];
        float cA = redD[j] + redD[Hn + j] + redD[2 * Hn + j] + redD[3 * Hn + j];
        float gl = gleak[j];
        float cmt = cmv[j] * (float)UNF;
        sCmt[j]   = cmt;
        sBaseN[j] = gl * vleak[j] + cC;
        sBaseD[j] = cmt + gl + cA + 1e-8f;
    }
    __syncthreads();

    float baseN = 0.f, baseD = 0.f, cmt = 0.f, vreg = 0.f;
    if (k == 0) { baseN = sBaseN[j]; baseD = sBaseD[j]; cmt = sCmt[j]; }

    for (int t = 0; t < Tn; ++t) {
        float ns = 0.f, ds = 0.f;
        if (k == 0) {
            int o = (t * Bn + b) * Hn + j;
            ns = NS[o];
            ds = DS[o];
        }
        #pragma unroll 1
        for (int u = 0; u < UNF; ++u) {
            float num = 0.f, den = 0.f;
            const float4* vp = reinterpret_cast<const float4*>(sv + k * 32);
            #pragma unroll
            for (int s4 = 0; s4 < 8; ++s4) {
                float4 vv = vp[s4];
                float vs[4] = {vv.x, vv.y, vv.z, vv.w};
                #pragma unroll
                for (int e = 0; e < 4; ++e) {
                    int s = s4 * 4 + e;
                    float arg = fmaf(vs[e], hsig[s], nhm[s]);
                    float th;
                    asm("tanh.approx.f32 %0, %1;" : "=f"(th) : "f"(arg));
                    float c = sC[(k * 32 + s) * Hn + j];
                    num = fmaf(c, th, num);
                    den = fmaf(fabsf(c), th, den);
                }
            }
            redN[k * Hn + j] = num;
            redD[k * Hn + j] = den;
            __syncthreads();
            if (k == 0) {
                float tn = redN[j] + redN[Hn + j] + redN[2 * Hn + j] + redN[3 * Hn + j]
                         + ns + baseN + cmt * vreg;
                float td = redD[j] + redD[Hn + j] + redD[2 * Hn + j] + redD[3 * Hn + j]
                         + ds + baseD;
                vreg = tn / td;
                sv[j] = vreg;
            }
            __syncthreads();
        }
        if (k == 0) out[(t * Bn + b) * Hn + j] = vreg;
    }
}

// ---------------------------------------------------------------------------
// Head GEMM: out_part = h[64,16384] @ W^T (W = [512,16384]), k-split by 8.
// grid (lt=16, head=2, ks=8), 128 threads, thread tile 4b x 4lat.
// ---------------------------------------------------------------------------
__global__ __launch_bounds__(128, 1)
void heads_kernel(const float* __restrict__ hseq,
                  const float* __restrict__ Wm, const float* __restrict__ Wl,
                  float* __restrict__ part)
{
    extern __shared__ float sm[];
    float* a_s = sm;               // [128][66] transposed h tile (j-major)
    float* w_s = sm + 128 * 66;    // [32][128]

    const int tid  = threadIdx.x;
    const int lt   = blockIdx.x;
    const int head = blockIdx.y;
    const int ks   = blockIdx.z;
    const float* W = head ? Wl : Wm;
    const int lat0 = lt * 32;
    const int bg   = tid & 15;     // b base = 4*bg
    const int lg   = tid >> 4;     // lat base = 4*lg

    float acc[4][4];
    #pragma unroll
    for (int a = 0; a < 4; ++a)
        #pragma unroll
        for (int c = 0; c < 4; ++c) acc[a][c] = 0.f;

    for (int t = ks * 16; t < ks * 16 + 16; ++t) {
        __syncthreads();
        // load h slab [64][128] transposed into a_s[j][b]
        const float* src = hseq + t * Bn * Hn;
        #pragma unroll
        for (int r = 0; r < 64; ++r) {
            int idx = r * 128 + tid;       // b = idx>>7, j = idx&127
            a_s[(idx & 127) * 66 + (idx >> 7)] = src[idx];
        }
        // load 32 W rows for this t
        #pragma unroll
        for (int r = 0; r < 32; ++r)
            w_s[r * 128 + tid] = W[(lat0 + r) * (Tn * Hn) + t * Hn + tid];
        __syncthreads();

        #pragma unroll 4
        for (int jj = 0; jj < 128; ++jj) {
            float2 a01 = *reinterpret_cast<const float2*>(&a_s[jj * 66 + bg * 4]);
            float2 a23 = *reinterpret_cast<const float2*>(&a_s[jj * 66 + bg * 4 + 2]);
            float av[4] = {a01.x, a01.y, a23.x, a23.y};
            float w0 = w_s[(lg * 4 + 0) * 128 + jj];
            float w1 = w_s[(lg * 4 + 1) * 128 + jj];
            float w2 = w_s[(lg * 4 + 2) * 128 + jj];
            float w3 = w_s[(lg * 4 + 3) * 128 + jj];
            #pragma unroll
            for (int bi = 0; bi < 4; ++bi) {
                acc[bi][0] = fmaf(av[bi], w0, acc[bi][0]);
                acc[bi][1] = fmaf(av[bi], w1, acc[bi][1]);
                acc[bi][2] = fmaf(av[bi], w2, acc[bi][2]);
                acc[bi][3] = fmaf(av[bi], w3, acc[bi][3]);
            }
        }
    }
    #pragma unroll
    for (int bi = 0; bi < 4; ++bi)
        #pragma unroll
        for (int li = 0; li < 4; ++li)
            part[(((ks * 2 + head) * Bn) + bg * 4 + bi) * LATn + lat0 + lg * 4 + li]
                = acc[bi][li];
}

// ---------------------------------------------------------------------------
// Epilogue: sum k-split partials, add bias, exp for sigma head.
// ---------------------------------------------------------------------------
__global__ __launch_bounds__(256)
void epilogue_kernel(const float* __restrict__ part,
                     const float* __restrict__ mu_b, const float* __restrict__ ls_b,
                     float* __restrict__ out)
{
    int idx  = blockIdx.x * 256 + threadIdx.x;   // 0..65535
    int head = idx >> 15;
    int r    = idx & 32767;                      // b*512 + lat
    int lat  = r & 511;
    float s = 0.f;
    #pragma unroll
    for (int ks = 0; ks < 8; ++ks)
        s += part[(ks * 2 + head) * Bn * LATn + r];
    s += head ? ls_b[lat] : mu_b[lat];
    out[idx] = head ? expf(s) : s;
}

// ---------------------------------------------------------------------------
// Launch
// ---------------------------------------------------------------------------
extern "C" void kernel_launch(void* const* d_in, const int* in_sizes, int n_in,
                              void* d_out, int out_size)
{
    const float* x      = (const float*)d_in[0];
    const float* gleak  = (const float*)d_in[1];
    const float* vleak  = (const float*)d_in[2];
    const float* cmv    = (const float*)d_in[3];
    const float* sigma  = (const float*)d_in[4];
    const float* mu_syn = (const float*)d_in[5];
    const float* w      = (const float*)d_in[6];
    const float* erev   = (const float*)d_in[7];
    const float* s_sig  = (const float*)d_in[8];
    const float* s_mu   = (const float*)d_in[9];
    const float* s_w    = (const float*)d_in[10];
    const float* s_ev   = (const float*)d_in[11];
    const float* mu_w   = (const float*)d_in[12];
    const float* mu_b   = (const float*)d_in[13];
    const float* ls_w   = (const float*)d_in[14];
    const float* ls_b   = (const float*)d_in[15];
    float* out = (float*)d_out;

    float *NS, *DS, *h0, *h1, *part;
    cudaGetSymbolAddress((void**)&NS,   g_NS);
    cudaGetSymbolAddress((void**)&DS,   g_DS);
    cudaGetSymbolAddress((void**)&h0,   g_h0);
    cudaGetSymbolAddress((void**)&h1,   g_h1);
    cudaGetSymbolAddress((void**)&part, g_part);

    const int SENS_SMEM = (3 * Hn * Hn + 16 * Hn) * 4;   // 204800 B
    const int LTC_SMEM  = 17920 * 4;                     // 71680 B
    const int GEMM_SMEM = (128 * 66 + 32 * 128) * 4;     // 50176 B
    cudaFuncSetAttribute(sensory_kernel, cudaFuncAttributeMaxDynamicSharedMemorySize, SENS_SMEM);
    cudaFuncSetAttribute(ltc_kernel,     cudaFuncAttributeMaxDynamicSharedMemorySize, LTC_SMEM);
    cudaFuncSetAttribute(heads_kernel,   cudaFuncAttributeMaxDynamicSharedMemorySize, GEMM_SMEM);

    // ---- layer 0 (input = x [B,T,F]: u[t][b][i] -> stride_t=F, stride_b=T*F)
    sensory_kernel<<<512, 128, SENS_SMEM>>>(x, Fn, Tn * Fn,
                                            s_sig, s_mu, s_w, s_ev, NS, DS);
    ltc_kernel<<<Bn, 512, LTC_SMEM>>>(sigma, mu_syn, w, erev,
                                      gleak, vleak, cmv, NS, DS, h0);
    // ---- layer 1 (input = h0 [T,B,H]: stride_t=B*H, stride_b=H)
    sensory_kernel<<<512, 128, SENS_SMEM>>>(h0, Bn * Hn, Hn,
                                            s_sig + Hn * Hn, s_mu + Hn * Hn,
                                            s_w + Hn * Hn, s_ev + Hn * Hn, NS, DS);
    ltc_kernel<<<Bn, 512, LTC_SMEM>>>(sigma + Hn * Hn, mu_syn + Hn * Hn,
                                      w + Hn * Hn, erev + Hn * Hn,
                                      gleak + Hn, vleak + Hn, cmv + Hn, NS, DS, h1);
    // ---- heads
    heads_kernel<<<dim3(16, 2, 8), 128, GEMM_SMEM>>>(h1, mu_w, ls_w, part);
    epilogue_kernel<<<(2 * Bn * LATn) / 256, 256>>>(part, mu_b, ls_b, out);
}

// round 3
// speedup vs baseline: 1.4631x; 1.4631x over previous
#include <cuda_runtime.h>
#include <cuda_fp16.h>
#include <cuda_bf16.h>

// Problem constants
#define Bn   64
#define Tn   128
#define Fn   128
#define Hn   128
#define LATn 512
#define UNF  6

// ---------------------------------------------------------------------------
// Device scratch (no allocations allowed)
// ---------------------------------------------------------------------------
__device__ float g_NS[Tn * Bn * Hn];          // layer-0 sensory numerator [t][b][j]
__device__ float g_DS[Tn * Bn * Hn];          // layer-0 sensory denominator
__device__ float g_NS1[Tn * Bn * Hn];         // layer-1 sensory num (produced by layer-0 blocks)
__device__ float g_DS1[Tn * Bn * Hn];         // layer-1 sensory den
__device__ float g_h1[Tn * Bn * Hn];          // layer-1 hidden seq (final)
__device__ float g_part[8 * 2 * Bn * LATn];   // head GEMM k-split partials
__device__ int   g_prog[Bn];                  // per-batch pipeline progress flags

// ---------------------------------------------------------------------------
// acquire / release helpers
// ---------------------------------------------------------------------------
__device__ __forceinline__ int ld_acq(const int* p) {
    int v;
    asm volatile("ld.global.acquire.gpu.b32 %0, [%1];" : "=r"(v) : "l"(p) : "memory");
    return v;
}
__device__ __forceinline__ void st_rel(int* p, int v) {
    asm volatile("st.global.release.gpu.b32 [%0], %1;" :: "l"(p), "r"(v) : "memory");
}

__global__ void init_kernel(int* prog) { prog[threadIdx.x] = 0; }

// ---------------------------------------------------------------------------
// Sensory precompute for layer 0: NS/DS[t,b,j] = const + sum_i C_ij*tanh(...)
// grid 512 x 128 threads; each block handles 16 (t,b) pairs, params in SMEM.
// ---------------------------------------------------------------------------
__global__ __launch_bounds__(128, 1)
void sensory_kernel(const float* __restrict__ U, int stride_t, int stride_b,
                    const float* __restrict__ ssig, const float* __restrict__ smu,
                    const float* __restrict__ sw,   const float* __restrict__ sev,
                    float* __restrict__ NS, float* __restrict__ DS)
{
    extern __shared__ float sm[];
    float* sHs = sm;                  // 16384
    float* sNh = sm + 16384;          // 16384
    float* sCc = sm + 32768;          // 16384
    float* su  = sm + 49152;          // 16*128

    const int j     = threadIdx.x;
    const int pair0 = blockIdx.x * 16;

    float cC = 0.f, cA = 0.f;
    for (int i = 0; i < Hn; ++i) {
        int idx = i * Hn + j;
        float sg = ssig[idx];
        float m  = smu[idx];
        sHs[idx] = 0.5f * sg;
        sNh[idx] = -0.5f * sg * m;
        float ww = sw[idx];
        float c  = 0.5f * ww * sev[idx];
        sCc[idx] = c;
        cC += c;
        cA += 0.5f * ww;
    }
    for (int p = 0; p < 16; ++p) {
        int pr = pair0 + p;
        int t  = pr >> 6;
        int b  = pr & 63;
        su[p * Hn + j] = U[t * stride_t + b * stride_b + j];
    }
    __syncthreads();

    for (int pg = 0; pg < 4; ++pg) {
        const float* u0 = su + (pg * 4 + 0) * Hn;
        const float* u1 = su + (pg * 4 + 1) * Hn;
        const float* u2 = su + (pg * 4 + 2) * Hn;
        const float* u3 = su + (pg * 4 + 3) * Hn;
        float n0 = cC, n1 = cC, n2 = cC, n3 = cC;
        float d0 = cA, d1 = cA, d2 = cA, d3 = cA;
        #pragma unroll 4
        for (int i = 0; i < Hn; ++i) {
            int idx = i * Hn + j;
            float hs = sHs[idx];
            float nh = sNh[idx];
            float c  = sCc[idx];
            float ac = fabsf(c);
            float t0, t1, t2, t3;
            float a0 = fmaf(u0[i], hs, nh);
            float a1 = fmaf(u1[i], hs, nh);
            float a2 = fmaf(u2[i], hs, nh);
            float a3 = fmaf(u3[i], hs, nh);
            asm("tanh.approx.f32 %0, %1;" : "=f"(t0) : "f"(a0));
            asm("tanh.approx.f32 %0, %1;" : "=f"(t1) : "f"(a1));
            asm("tanh.approx.f32 %0, %1;" : "=f"(t2) : "f"(a2));
            asm("tanh.approx.f32 %0, %1;" : "=f"(t3) : "f"(a3));
            n0 = fmaf(c, t0, n0);  d0 = fmaf(ac, t0, d0);
            n1 = fmaf(c, t1, n1);  d1 = fmaf(ac, t1, d1);
            n2 = fmaf(c, t2, n2);  d2 = fmaf(ac, t2, d2);
            n3 = fmaf(c, t3, n3);  d3 = fmaf(ac, t3, d3);
        }
        int o = (pair0 + pg * 4) * Hn + j;
        NS[o]          = n0;  DS[o]          = d0;
        NS[o + Hn]     = n1;  DS[o + Hn]     = d1;
        NS[o + 2 * Hn] = n2;  DS[o + 2 * Hn] = d2;
        NS[o + 3 * Hn] = n3;  DS[o + 3 * Hn] = d3;
    }
}

// ---------------------------------------------------------------------------
// Pipelined dual-layer LTC. grid = 128: block < 64 -> layer 0 batch b,
// block >= 64 -> layer 1 batch b. 512 threads: j = tid&127, k = tid>>7,
// lane = tid&31, p = 32k + lane.
//
// Thread (j,k) accumulates partials for column j over i in [32k, 32k+32).
// Every thread redundantly computes the new state v_p for p = 32k+lane;
// since a warp has constant k and lanes 0..31, the warp collectively holds
// exactly v_i for its own i-range -> inner-loop v comes from __shfl_sync.
// One __syncthreads per unfold (partial arrays double-buffered by parity).
//
// Layer-0 blocks also compute layer-1's sensory NS1/DS1 inline from v(t)
// (half2-packed params in SMEM) and release a per-batch progress flag.
// ---------------------------------------------------------------------------
__global__ __launch_bounds__(512, 1)
void pipe_kernel(const float* __restrict__ sigma, const float* __restrict__ mu,
                 const float* __restrict__ w,     const float* __restrict__ erev,
                 const float* __restrict__ gleak, const float* __restrict__ vleak,
                 const float* __restrict__ cmv,
                 const float* __restrict__ s_sig, const float* __restrict__ s_mu,
                 const float* __restrict__ s_w,   const float* __restrict__ s_ev,
                 const float* __restrict__ NS0,   const float* __restrict__ DS0,
                 float* __restrict__ NS1,         float* __restrict__ DS1,
                 float* __restrict__ h1,          int* __restrict__ prog)
{
    extern __shared__ float sm[];
    float* sC   = sm;                        // 16384 : recurrent C (fp32)
    float* redN = sm + 16384;                // 2 x 512 (parity buffers)
    float* redD = sm + 17408;                // 2 x 512
    float* senN = sm + 18432;                // 512
    float* senD = sm + 18944;                // 512
    half2* sA   = (half2*)(sm + 19456);      // 16384 x (hs, nh)
    half2* sB   = (half2*)(sm + 35840);      // 16384 x (c, |c|)

    const int layer = blockIdx.x >> 6;
    const int b     = blockIdx.x & 63;
    const int tid   = threadIdx.x;
    const int j     = tid & 127;
    const int k     = tid >> 7;
    const int lane  = tid & 31;
    const int p     = k * 32 + lane;
    const int lofsM = layer * Hn * Hn;
    const int lofsV = layer * Hn;

    // ---- recurrent params: hsig/nhm in regs, C in SMEM, column sums staged
    float hsig[32], nhm[32];
    {
        float cpart = 0.f, apart = 0.f;
        #pragma unroll
        for (int s = 0; s < 32; ++s) {
            int idx = (k * 32 + s) * Hn + j;
            float sg = sigma[lofsM + idx];
            float m  = mu[lofsM + idx];
            hsig[s] = 0.5f * sg;
            nhm[s]  = -0.5f * sg * m;
            float ww = w[lofsM + idx];
            float c  = 0.5f * ww * erev[lofsM + idx];
            sC[idx] = c;
            cpart += c;
            apart += 0.5f * ww;
        }
        redN[k * Hn + j] = cpart;
        redD[k * Hn + j] = apart;
    }

    // ---- layer-0 blocks: stage layer-1 sensory params as packed half2
    if (layer == 0) {
        float csum = 0.f, asum = 0.f;
        #pragma unroll
        for (int s = 0; s < 32; ++s) {
            int idx = (k * 32 + s) * Hn + j;
            float sg = s_sig[idx];
            float m  = s_mu[idx];
            float ww = s_w[idx];
            float ev = s_ev[idx];
            sA[idx] = __floats2half2_rn(0.5f * sg, -0.5f * sg * m);
            float c = 0.5f * ww * ev;
            sB[idx] = __floats2half2_rn(c, 0.5f * ww);
            csum += c;
            asum += 0.5f * ww;
        }
        senN[k * Hn + j] = csum;
        senD[k * Hn + j] = asum;
    }
    __syncthreads();

    // per-p constants live in registers
    float cC = redN[p] + redN[Hn + p] + redN[2 * Hn + p] + redN[3 * Hn + p];
    float cA = redD[p] + redD[Hn + p] + redD[2 * Hn + p] + redD[3 * Hn + p];
    const float gl    = gleak[lofsV + p];
    const float cmt   = cmv[lofsV + p] * (float)UNF;
    const float baseN = gl * vleak[lofsV + p] + cC;
    const float baseD = cmt + gl + cA + 1e-8f;
    float csN = 0.f, csA = 0.f;
    if (layer == 0) {
        csN = senN[p] + senN[Hn + p] + senN[2 * Hn + p] + senN[3 * Hn + p];
        csA = senD[p] + senD[Hn + p] + senD[2 * Hn + p] + senD[3 * Hn + p];
    }
    __syncthreads();

    float vreg = 0.f;   // recurrent state v_p

    for (int t = 0; t < Tn; ++t) {
        const int o = (t * Bn + b) * Hn;
        float ns, ds;
        if (layer == 0) {
            ns = NS0[o + p];
            ds = DS0[o + p];
        } else {
            if (tid == 0) {
                while (ld_acq(&prog[b]) < t + 1) __nanosleep(64);
            }
            __syncthreads();
            ns = __ldcg(NS1 + o + p);
            ds = __ldcg(DS1 + o + p);
        }

        #pragma unroll 1
        for (int u = 0; u < UNF; ++u) {
            const int pr = (u & 1) * 512;
            float num = 0.f, den = 0.f;
            #pragma unroll
            for (int s = 0; s < 32; ++s) {
                float vs = __shfl_sync(0xffffffffu, vreg, s);
                float arg = fmaf(vs, hsig[s], nhm[s]);
                float th;
                asm("tanh.approx.f32 %0, %1;" : "=f"(th) : "f"(arg));
                float c = sC[(k * 32 + s) * Hn + j];
                num = fmaf(c, th, num);
                den = fmaf(fabsf(c), th, den);
            }
            redN[pr + k * Hn + j] = num;
            redD[pr + k * Hn + j] = den;
            __syncthreads();
            float rn = redN[pr + p] + redN[pr + Hn + p]
                     + redN[pr + 2 * Hn + p] + redN[pr + 3 * Hn + p];
            float rd = redD[pr + p] + redD[pr + Hn + p]
                     + redD[pr + 2 * Hn + p] + redD[pr + 3 * Hn + p];
            float tn = rn + ns + baseN + cmt * vreg;
            float td = rd + ds + baseD;
            vreg = __fdividef(tn, td);
        }

        if (layer == 0) {
            // inline sensory pass for layer 1 using v(t) via shuffles
            float nsum = 0.f, dsum = 0.f;
            #pragma unroll
            for (int s = 0; s < 32; ++s) {
                float vs = __shfl_sync(0xffffffffu, vreg, s);
                int idx = (k * 32 + s) * Hn + j;
                float2 a = __half22float2(sA[idx]);
                float arg = fmaf(vs, a.x, a.y);
                float th;
                asm("tanh.approx.f32 %0, %1;" : "=f"(th) : "f"(arg));
                float2 cc = __half22float2(sB[idx]);
                nsum = fmaf(cc.x, th, nsum);
                dsum = fmaf(cc.y, th, dsum);
            }
            senN[k * Hn + j] = nsum;
            senD[k * Hn + j] = dsum;
            __syncthreads();
            if (((tid >> 5) & 3) == 0) {
                float nn = senN[p] + senN[Hn + p] + senN[2 * Hn + p] + senN[3 * Hn + p] + csN;
                float dd = senD[p] + senD[Hn + p] + senD[2 * Hn + p] + senD[3 * Hn + p] + csA;
                NS1[o + p] = nn;
                DS1[o + p] = dd;
            }
            __threadfence();
            __syncthreads();
            if (tid == 0) st_rel(&prog[b], t + 1);
        } else {
            if (((tid >> 5) & 3) == 0) h1[o + p] = vreg;
        }
    }
}

// ---------------------------------------------------------------------------
// Head GEMM: out_part = h[64,16384] @ W^T (W = [512,16384]), k-split by 8.
// ---------------------------------------------------------------------------
__global__ __launch_bounds__(128, 1)
void heads_kernel(const float* __restrict__ hseq,
                  const float* __restrict__ Wm, const float* __restrict__ Wl,
                  float* __restrict__ part)
{
    extern __shared__ float sm[];
    float* a_s = sm;               // [128][66] transposed h tile
    float* w_s = sm + 128 * 66;    // [32][128]

    const int tid  = threadIdx.x;
    const int lt   = blockIdx.x;
    const int head = blockIdx.y;
    const int ks   = blockIdx.z;
    const float* W = head ? Wl : Wm;
    const int lat0 = lt * 32;
    const int bg   = tid & 15;
    const int lg   = tid >> 4;

    float acc[4][4];
    #pragma unroll
    for (int a = 0; a < 4; ++a)
        #pragma unroll
        for (int c = 0; c < 4; ++c) acc[a][c] = 0.f;

    for (int t = ks * 16; t < ks * 16 + 16; ++t) {
        __syncthreads();
        const float* src = hseq + t * Bn * Hn;
        #pragma unroll
        for (int r = 0; r < 64; ++r) {
            int idx = r * 128 + tid;
            a_s[(idx & 127) * 66 + (idx >> 7)] = src[idx];
        }
        #pragma unroll
        for (int r = 0; r < 32; ++r)
            w_s[r * 128 + tid] = W[(lat0 + r) * (Tn * Hn) + t * Hn + tid];
        __syncthreads();

        #pragma unroll 4
        for (int jj = 0; jj < 128; ++jj) {
            float2 a01 = *reinterpret_cast<const float2*>(&a_s[jj * 66 + bg * 4]);
            float2 a23 = *reinterpret_cast<const float2*>(&a_s[jj * 66 + bg * 4 + 2]);
            float av[4] = {a01.x, a01.y, a23.x, a23.y};
            float w0 = w_s[(lg * 4 + 0) * 128 + jj];
            float w1 = w_s[(lg * 4 + 1) * 128 + jj];
            float w2 = w_s[(lg * 4 + 2) * 128 + jj];
            float w3 = w_s[(lg * 4 + 3) * 128 + jj];
            #pragma unroll
            for (int bi = 0; bi < 4; ++bi) {
                acc[bi][0] = fmaf(av[bi], w0, acc[bi][0]);
                acc[bi][1] = fmaf(av[bi], w1, acc[bi][1]);
                acc[bi][2] = fmaf(av[bi], w2, acc[bi][2]);
                acc[bi][3] = fmaf(av[bi], w3, acc[bi][3]);
            }
        }
    }
    #pragma unroll
    for (int bi = 0; bi < 4; ++bi)
        #pragma unroll
        for (int li = 0; li < 4; ++li)
            part[(((ks * 2 + head) * Bn) + bg * 4 + bi) * LATn + lat0 + lg * 4 + li]
                = acc[bi][li];
}

// ---------------------------------------------------------------------------
// Epilogue: sum k-split partials, add bias, exp for sigma head.
// ---------------------------------------------------------------------------
__global__ __launch_bounds__(256)
void epilogue_kernel(const float* __restrict__ part,
                     const float* __restrict__ mu_b, const float* __restrict__ ls_b,
                     float* __restrict__ out)
{
    int idx  = blockIdx.x * 256 + threadIdx.x;
    int head = idx >> 15;
    int r    = idx & 32767;
    int lat  = r & 511;
    float s = 0.f;
    #pragma unroll
    for (int ks = 0; ks < 8; ++ks)
        s += part[(ks * 2 + head) * Bn * LATn + r];
    s += head ? ls_b[lat] : mu_b[lat];
    out[idx] = head ? expf(s) : s;
}

// ---------------------------------------------------------------------------
// Launch
// ---------------------------------------------------------------------------
extern "C" void kernel_launch(void* const* d_in, const int* in_sizes, int n_in,
                              void* d_out, int out_size)
{
    const float* x      = (const float*)d_in[0];
    const float* gleak  = (const float*)d_in[1];
    const float* vleak  = (const float*)d_in[2];
    const float* cmv    = (const float*)d_in[3];
    const float* sigma  = (const float*)d_in[4];
    const float* mu_syn = (const float*)d_in[5];
    const float* w      = (const float*)d_in[6];
    const float* erev   = (const float*)d_in[7];
    const float* s_sig  = (const float*)d_in[8];
    const float* s_mu   = (const float*)d_in[9];
    const float* s_w    = (const float*)d_in[10];
    const float* s_ev   = (const float*)d_in[11];
    const float* mu_w   = (const float*)d_in[12];
    const float* mu_b   = (const float*)d_in[13];
    const float* ls_w   = (const float*)d_in[14];
    const float* ls_b   = (const float*)d_in[15];
    float* out = (float*)d_out;

    float *NS, *DS, *NS1, *DS1, *h1, *part;
    int* prog;
    cudaGetSymbolAddress((void**)&NS,   g_NS);
    cudaGetSymbolAddress((void**)&DS,   g_DS);
    cudaGetSymbolAddress((void**)&NS1,  g_NS1);
    cudaGetSymbolAddress((void**)&DS1,  g_DS1);
    cudaGetSymbolAddress((void**)&h1,   g_h1);
    cudaGetSymbolAddress((void**)&part, g_part);
    cudaGetSymbolAddress((void**)&prog, g_prog);

    const int SENS_SMEM = (3 * Hn * Hn + 16 * Hn) * 4;       // 204800 B
    const int PIPE_SMEM = 52224 * 4;                         // 208896 B
    const int GEMM_SMEM = (128 * 66 + 32 * 128) * 4;         // 50176 B
    cudaFuncSetAttribute(sensory_kernel, cudaFuncAttributeMaxDynamicSharedMemorySize, SENS_SMEM);
    cudaFuncSetAttribute(pipe_kernel,    cudaFuncAttributeMaxDynamicSharedMemorySize, PIPE_SMEM);
    cudaFuncSetAttribute(heads_kernel,   cudaFuncAttributeMaxDynamicSharedMemorySize, GEMM_SMEM);

    init_kernel<<<1, Bn>>>(prog);
    // layer-0 sensory from x [B,T,F]: u[t][b][i] -> stride_t=F, stride_b=T*F
    sensory_kernel<<<512, 128, SENS_SMEM>>>(x, Fn, Tn * Fn,
                                            s_sig, s_mu, s_w, s_ev, NS, DS);
    // pipelined dual-layer recurrence (layer-1 sensory params offset by H*H)
    pipe_kernel<<<128, 512, PIPE_SMEM>>>(sigma, mu_syn, w, erev, gleak, vleak, cmv,
                                         s_sig + Hn * Hn, s_mu + Hn * Hn,
                                         s_w + Hn * Hn, s_ev + Hn * Hn,
                                         NS, DS, NS1, DS1, h1, prog);
    // heads
    heads_kernel<<<dim3(16, 2, 8), 128, GEMM_SMEM>>>(h1, mu_w, ls_w, part);
    epilogue_kernel<<<(2 * Bn * LATn) / 256, 256>>>(part, mu_b, ls_b, out);
}

// round 5
// speedup vs baseline: 1.5006x; 1.0256x over previous
#include <cuda_runtime.h>
#include <cuda_fp16.h>
#include <cuda_bf16.h>

// Problem constants
#define Bn   64
#define Tn   128
#define Fn   128
#define Hn   128
#define LATn 512
#define UNF  6
#define PADW 132   // padded row stride (words) for conflict-free LDS.128

// ---------------------------------------------------------------------------
// Device scratch (no allocations allowed)
// ---------------------------------------------------------------------------
__device__ float2 g_ND0[Tn * Bn * Hn];         // layer-0 sensory (num,den)
__device__ float2 g_ND1[Tn * Bn * Hn];         // layer-1 sensory (num,den)
__device__ float  g_h1[Tn * Bn * Hn];          // layer-1 hidden seq (final)
__device__ float  g_part[16 * 2 * Bn * LATn];  // head GEMM k-split partials
__device__ int    g_prog[Bn];                  // per-batch pipeline progress

// ---------------------------------------------------------------------------
// acquire / release helpers
// ---------------------------------------------------------------------------
__device__ __forceinline__ int ld_acq(const int* p) {
    int v;
    asm volatile("ld.global.acquire.gpu.b32 %0, [%1];" : "=r"(v) : "l"(p) : "memory");
    return v;
}
__device__ __forceinline__ void st_rel(int* p, int v) {
    asm volatile("st.global.release.gpu.b32 [%0], %1;" :: "l"(p), "r"(v) : "memory");
}

__global__ void init_kernel(int* prog) { prog[threadIdx.x] = 0; }

// ---------------------------------------------------------------------------
// Layer-0 sensory precompute. grid 512 x 256 threads.
// Params transposed to [j][PADW] fp32 in SMEM, vectorized LDS.128.
// Each block: 16 (t,b) pairs; thread (j = tid&127, half = tid>>7) handles
// 8 pairs (2 groups of 4). Outputs packed float2 (num,den).
// ---------------------------------------------------------------------------
__global__ __launch_bounds__(256, 1)
void sensory_kernel(const float* __restrict__ U, int stride_t, int stride_b,
                    const float* __restrict__ ssig, const float* __restrict__ smu,
                    const float* __restrict__ sw,   const float* __restrict__ sev,
                    float2* __restrict__ ND)
{
    extern __shared__ float sm[];
    float* sHs = sm;                      // [128][PADW]
    float* sNh = sm + 128 * PADW;         // [128][PADW]
    float* sCc = sm + 2 * 128 * PADW;     // [128][PADW]
    float* su  = sm + 3 * 128 * PADW;     // [16][128]

    const int tid   = threadIdx.x;
    const int j     = tid & 127;
    const int half  = tid >> 7;
    const int pair0 = blockIdx.x * 16;

    // stage params transposed
    for (int idx = tid; idx < Hn * Hn; idx += 256) {
        int i  = idx >> 7;
        int jj = idx & 127;
        float sg = ssig[idx];
        float m  = smu[idx];
        sHs[jj * PADW + i] = 0.5f * sg;
        sNh[jj * PADW + i] = -0.5f * sg * m;
        sCc[jj * PADW + i] = 0.5f * sw[idx] * sev[idx];
    }
    // stage inputs
    for (int idx = tid; idx < 16 * Hn; idx += 256) {
        int p  = idx >> 7;
        int i  = idx & 127;
        int pr = pair0 + p;
        int t  = pr >> 6;
        int b  = pr & 63;
        su[idx] = U[t * stride_t + b * stride_b + i];
    }
    __syncthreads();

    // per-j constant sums
    float cC = 0.f, cA = 0.f;
    {
        const float4* cr = (const float4*)(sCc + j * PADW);
        #pragma unroll 8
        for (int q = 0; q < 32; ++q) {
            float4 c4 = cr[q];
            cC += c4.x + c4.y + c4.z + c4.w;
            cA += fabsf(c4.x) + fabsf(c4.y) + fabsf(c4.z) + fabsf(c4.w);
        }
    }

    const float4* hsr = (const float4*)(sHs + j * PADW);
    const float4* nhr = (const float4*)(sNh + j * PADW);
    const float4* ccr = (const float4*)(sCc + j * PADW);

    for (int pg2 = 0; pg2 < 2; ++pg2) {
        const int pg = half * 2 + pg2;
        const float4* u0r = (const float4*)(su + (pg * 4 + 0) * Hn);
        const float4* u1r = (const float4*)(su + (pg * 4 + 1) * Hn);
        const float4* u2r = (const float4*)(su + (pg * 4 + 2) * Hn);
        const float4* u3r = (const float4*)(su + (pg * 4 + 3) * Hn);
        float n0 = cC, n1 = cC, n2 = cC, n3 = cC;
        float d0 = cA, d1 = cA, d2 = cA, d3 = cA;
        #pragma unroll 4
        for (int q = 0; q < 32; ++q) {
            float4 hs = hsr[q], nh = nhr[q], cc = ccr[q];
            float4 u0 = u0r[q], u1 = u1r[q], u2 = u2r[q], u3 = u3r[q];
            #pragma unroll
            for (int e = 0; e < 4; ++e) {
                float hse = (&hs.x)[e];
                float nhe = (&nh.x)[e];
                float c   = (&cc.x)[e];
                float ac  = fabsf(c);
                float t0, t1, t2, t3;
                float a0 = fmaf((&u0.x)[e], hse, nhe);
                float a1 = fmaf((&u1.x)[e], hse, nhe);
                float a2 = fmaf((&u2.x)[e], hse, nhe);
                float a3 = fmaf((&u3.x)[e], hse, nhe);
                asm("tanh.approx.f32 %0, %1;" : "=f"(t0) : "f"(a0));
                asm("tanh.approx.f32 %0, %1;" : "=f"(t1) : "f"(a1));
                asm("tanh.approx.f32 %0, %1;" : "=f"(t2) : "f"(a2));
                asm("tanh.approx.f32 %0, %1;" : "=f"(t3) : "f"(a3));
                n0 = fmaf(c, t0, n0);  d0 = fmaf(ac, t0, d0);
                n1 = fmaf(c, t1, n1);  d1 = fmaf(ac, t1, d1);
                n2 = fmaf(c, t2, n2);  d2 = fmaf(ac, t2, d2);
                n3 = fmaf(c, t3, n3);  d3 = fmaf(ac, t3, d3);
            }
        }
        int o = (pair0 + pg * 4) * Hn + j;
        ND[o]          = make_float2(n0, d0);
        ND[o + Hn]     = make_float2(n1, d1);
        ND[o + 2 * Hn] = make_float2(n2, d2);
        ND[o + 3 * Hn] = make_float2(n3, d3);
    }
}

// ---------------------------------------------------------------------------
// Pipelined dual-layer LTC. grid = 128: block < 64 -> layer 0 batch b,
// block >= 64 -> layer 1 batch b. 512 threads: j = tid&127, k = tid>>7.
// Per unfold: all threads read v via broadcast LDS.128 from sv (double-
// buffered by parity), compute partials with vectorized sC reads, write
// float2 partial sums; barrier; 4 "writer" warps (j-group 0) reduce,
// divide, write sv[next parity]; barrier.
// Layer-0 blocks also compute layer-1's sensory ND1 inline (half2 params,
// transposed) and release a per-batch progress flag.
// ---------------------------------------------------------------------------
__global__ __launch_bounds__(512, 1)
void pipe_kernel(const float* __restrict__ sigma, const float* __restrict__ mu,
                 const float* __restrict__ w,     const float* __restrict__ erev,
                 const float* __restrict__ gleak, const float* __restrict__ vleak,
                 const float* __restrict__ cmv,
                 const float* __restrict__ s_sig, const float* __restrict__ s_mu,
                 const float* __restrict__ s_w,   const float* __restrict__ s_ev,
                 const float2* __restrict__ ND0,  float2* __restrict__ ND1,
                 float* __restrict__ h1,          int* __restrict__ prog)
{
    extern __shared__ float sm[];
    float*  sC    = sm;                                  // [128][PADW] fp32
    float*  sv    = sm + 128 * PADW;                     // 2 x 128 (parity)
    float2* redND = (float2*)(sm + 128 * PADW + 256);    // 2 x 512 float2
    float2* senND = redND + 1024;                        // 512 float2
    half2*  sA    = (half2*)(senND + 512);               // [128][PADW] (hs,nh)
    half2*  sB    = sA + 128 * PADW;                     // [128][PADW] (c,|c|)

    const int layer = blockIdx.x >> 6;
    const int b     = blockIdx.x & 63;
    const int tid   = threadIdx.x;
    const int j     = tid & 127;
    const int k     = tid >> 7;
    const int lane  = tid & 31;
    const int p     = k * 32 + lane;
    const bool wrt  = ((tid >> 5) & 3) == 0;   // warps 0,4,8,12: j-group 0
    const int lofsM = layer * Hn * Hn;
    const int lofsV = layer * Hn;

    // ---- stage recurrent params: hsig/nhm regs, sC transposed [j][i]
    float hsig[32], nhm[32];
    {
        float cpart = 0.f, apart = 0.f;
        #pragma unroll
        for (int s = 0; s < 32; ++s) {
            int i   = k * 32 + s;
            int idx = i * Hn + j;
            float sg = sigma[lofsM + idx];
            float m  = mu[lofsM + idx];
            hsig[s] = 0.5f * sg;
            nhm[s]  = -0.5f * sg * m;
            float ww = w[lofsM + idx];
            float c  = 0.5f * ww * erev[lofsM + idx];
            sC[j * PADW + i] = c;
            cpart += c;
            apart += 0.5f * ww;
        }
        redND[k * 128 + j] = make_float2(cpart, apart);
    }
    if (tid < 128) sv[tid] = 0.f;   // parity-0 buffer

    // ---- layer-0: stage layer-1 sensory params transposed, half2 packed
    if (layer == 0) {
        float csum = 0.f, asum = 0.f;
        #pragma unroll
        for (int s = 0; s < 32; ++s) {
            int i   = k * 32 + s;
            int idx = i * Hn + j;
            float sg = s_sig[idx];
            float m  = s_mu[idx];
            float ww = s_w[idx];
            float ev = s_ev[idx];
            sA[j * PADW + i] = __floats2half2_rn(0.5f * sg, -0.5f * sg * m);
            float c = 0.5f * ww * ev;
            sB[j * PADW + i] = __floats2half2_rn(c, 0.5f * ww);
            csum += c;
            asum += 0.5f * ww;
        }
        senND[k * 128 + j] = make_float2(csum, asum);
    }
    __syncthreads();

    // per-p constants (all threads compute; writers use them)
    float2 c0 = redND[p], c1 = redND[128 + p], c2 = redND[256 + p], c3 = redND[384 + p];
    float cC = c0.x + c1.x + c2.x + c3.x;
    float cA = c0.y + c1.y + c2.y + c3.y;
    const float gl    = gleak[lofsV + p];
    const float cmt   = cmv[lofsV + p] * (float)UNF;
    const float baseN = gl * vleak[lofsV + p] + cC;
    const float baseD = cmt + gl + cA + 1e-8f;
    float csN = 0.f, csA = 0.f;
    if (layer == 0) {
        float2 s0 = senND[p], s1 = senND[128 + p], s2 = senND[256 + p], s3 = senND[384 + p];
        csN = s0.x + s1.x + s2.x + s3.x;
        csA = s0.y + s1.y + s2.y + s3.y;
    }
    __syncthreads();

    const float4* crow = (const float4*)(sC + j * PADW + 32 * k);
    const float4* arow = (const float4*)(sA + j * PADW + 32 * k);   // 8 x (4 half2)
    const float4* brow = (const float4*)(sB + j * PADW + 32 * k);   // 8 x (4 half2)

    float vreg = 0.f;   // writer warps: recurrent state v_p

    for (int t = 0; t < Tn; ++t) {
        const int o = (t * Bn + b) * Hn;
        float ns = 0.f, ds = 0.f;
        if (layer == 0) {
            if (wrt) { float2 nd = ND0[o + p]; ns = nd.x; ds = nd.y; }
        } else {
            if (tid == 0) {
                while (ld_acq(&prog[b]) < t + 1) __nanosleep(64);
            }
            __syncthreads();
            if (wrt) { float2 nd = __ldcg(ND1 + o + p); ns = nd.x; ds = nd.y; }
        }

        #pragma unroll 1
        for (int u = 0; u < UNF; ++u) {
            const int par = u & 1;
            const float4* vrow = (const float4*)(sv + par * 128 + 32 * k);
            float num = 0.f, den = 0.f;
            #pragma unroll
            for (int s4 = 0; s4 < 8; ++s4) {
                float4 v4 = vrow[s4];
                float4 c4 = crow[s4];
                #pragma unroll
                for (int e = 0; e < 4; ++e) {
                    int s = s4 * 4 + e;
                    float arg = fmaf((&v4.x)[e], hsig[s], nhm[s]);
                    float th;
                    asm("tanh.approx.f32 %0, %1;" : "=f"(th) : "f"(arg));
                    float c = (&c4.x)[e];
                    num = fmaf(c, th, num);
                    den = fmaf(fabsf(c), th, den);
                }
            }
            redND[par * 512 + k * 128 + j] = make_float2(num, den);
            __syncthreads();
            if (wrt) {
                const float2* rp = redND + par * 512;
                float2 r0 = rp[p], r1 = rp[128 + p], r2 = rp[256 + p], r3 = rp[384 + p];
                float rn = r0.x + r1.x + r2.x + r3.x;
                float rd = r0.y + r1.y + r2.y + r3.y;
                float tn = rn + ns + baseN + cmt * vreg;
                float td = rd + ds + baseD;
                vreg = __fdividef(tn, td);
                sv[(par ^ 1) * 128 + p] = vreg;
            }
            __syncthreads();
        }
        // after UNF=6 unfolds, v(t) is in sv parity 0 (and writers' vreg)

        if (layer == 0) {
            // inline sensory pass for layer 1 from sv parity-0.
            // Each float4 of params = 4 half2 = 4 i-entries, paired with one
            // float4 of v (4 values). 8 groups cover the 32-entry i-range.
            const float4* vrow = (const float4*)(sv + 32 * k);
            float nsum = 0.f, dsum = 0.f;
            #pragma unroll
            for (int g = 0; g < 8; ++g) {
                float4 v4 = vrow[g];
                float4 a4 = arow[g];
                float4 b4 = brow[g];
                const half2* ah = reinterpret_cast<const half2*>(&a4);
                const half2* bh = reinterpret_cast<const half2*>(&b4);
                #pragma unroll
                for (int e = 0; e < 4; ++e) {
                    float vs = (&v4.x)[e];
                    float2 a = __half22float2(ah[e]);
                    float arg = fmaf(vs, a.x, a.y);
                    float th;
                    asm("tanh.approx.f32 %0, %1;" : "=f"(th) : "f"(arg));
                    float2 cc = __half22float2(bh[e]);
                    nsum = fmaf(cc.x, th, nsum);
                    dsum = fmaf(cc.y, th, dsum);
                }
            }
            senND[k * 128 + j] = make_float2(nsum, dsum);
            __syncthreads();
            if (wrt) {
                float2 s0 = senND[p], s1 = senND[128 + p], s2 = senND[256 + p], s3 = senND[384 + p];
                float nn = s0.x + s1.x + s2.x + s3.x + csN;
                float dd = s0.y + s1.y + s2.y + s3.y + csA;
                ND1[o + p] = make_float2(nn, dd);
            }
            __threadfence();
            __syncthreads();
            if (tid == 0) st_rel(&prog[b], t + 1);
        } else {
            if (wrt) h1[o + p] = vreg;
        }
    }
}

// ---------------------------------------------------------------------------
// Head GEMM: out_part = h[64,16384] @ W^T (W = [512,16384]), k-split by 16.
// ---------------------------------------------------------------------------
__global__ __launch_bounds__(128)
void heads_kernel(const float* __restrict__ hseq,
                  const float* __restrict__ Wm, const float* __restrict__ Wl,
                  float* __restrict__ part)
{
    extern __shared__ float sm[];
    float* a_s = sm;               // [128][66] transposed h tile
    float* w_s = sm + 128 * 66;    // [32][128]

    const int tid  = threadIdx.x;
    const int lt   = blockIdx.x;
    const int head = blockIdx.y;
    const int ks   = blockIdx.z;
    const float* W = head ? Wl : Wm;
    const int lat0 = lt * 32;
    const int bg   = tid & 15;
    const int lg   = tid >> 4;

    float acc[4][4];
    #pragma unroll
    for (int a = 0; a < 4; ++a)
        #pragma unroll
        for (int c = 0; c < 4; ++c) acc[a][c] = 0.f;

    for (int t = ks * 8; t < ks * 8 + 8; ++t) {
        __syncthreads();
        const float* src = hseq + t * Bn * Hn;
        #pragma unroll
        for (int r = 0; r < 64; ++r) {
            int idx = r * 128 + tid;
            a_s[(idx & 127) * 66 + (idx >> 7)] = src[idx];
        }
        #pragma unroll
        for (int r = 0; r < 32; ++r)
            w_s[r * 128 + tid] = W[(lat0 + r) * (Tn * Hn) + t * Hn + tid];
        __syncthreads();

        #pragma unroll 4
        for (int jj = 0; jj < 128; ++jj) {
            float2 a01 = *reinterpret_cast<const float2*>(&a_s[jj * 66 + bg * 4]);
            float2 a23 = *reinterpret_cast<const float2*>(&a_s[jj * 66 + bg * 4 + 2]);
            float av[4] = {a01.x, a01.y, a23.x, a23.y};
            float w0 = w_s[(lg * 4 + 0) * 128 + jj];
            float w1 = w_s[(lg * 4 + 1) * 128 + jj];
            float w2 = w_s[(lg * 4 + 2) * 128 + jj];
            float w3 = w_s[(lg * 4 + 3) * 128 + jj];
            #pragma unroll
            for (int bi = 0; bi < 4; ++bi) {
                acc[bi][0] = fmaf(av[bi], w0, acc[bi][0]);
                acc[bi][1] = fmaf(av[bi], w1, acc[bi][1]);
                acc[bi][2] = fmaf(av[bi], w2, acc[bi][2]);
                acc[bi][3] = fmaf(av[bi], w3, acc[bi][3]);
            }
        }
    }
    #pragma unroll
    for (int bi = 0; bi < 4; ++bi)
        #pragma unroll
        for (int li = 0; li < 4; ++li)
            part[(((ks * 2 + head) * Bn) + bg * 4 + bi) * LATn + lat0 + lg * 4 + li]
                = acc[bi][li];
}

// ---------------------------------------------------------------------------
// Epilogue: sum k-split partials, add bias, exp for sigma head.
// ---------------------------------------------------------------------------
__global__ __launch_bounds__(256)
void epilogue_kernel(const float* __restrict__ part,
                     const float* __restrict__ mu_b, const float* __restrict__ ls_b,
                     float* __restrict__ out)
{
    int idx  = blockIdx.x * 256 + threadIdx.x;
    int head = idx >> 15;
    int r    = idx & 32767;
    int lat  = r & 511;
    float s = 0.f;
    #pragma unroll
    for (int ks = 0; ks < 16; ++ks)
        s += part[(ks * 2 + head) * Bn * LATn + r];
    s += head ? ls_b[lat] : mu_b[lat];
    out[idx] = head ? expf(s) : s;
}

// ---------------------------------------------------------------------------
// Launch
// ---------------------------------------------------------------------------
extern "C" void kernel_launch(void* const* d_in, const int* in_sizes, int n_in,
                              void* d_out, int out_size)
{
    const float* x      = (const float*)d_in[0];
    const float* gleak  = (const float*)d_in[1];
    const float* vleak  = (const float*)d_in[2];
    const float* cmv    = (const float*)d_in[3];
    const float* sigma  = (const float*)d_in[4];
    const float* mu_syn = (const float*)d_in[5];
    const float* w      = (const float*)d_in[6];
    const float* erev   = (const float*)d_in[7];
    const float* s_sig  = (const float*)d_in[8];
    const float* s_mu   = (const float*)d_in[9];
    const float* s_w    = (const float*)d_in[10];
    const float* s_ev   = (const float*)d_in[11];
    const float* mu_w   = (const float*)d_in[12];
    const float* mu_b   = (const float*)d_in[13];
    const float* ls_w   = (const float*)d_in[14];
    const float* ls_b   = (const float*)d_in[15];
    float* out = (float*)d_out;

    float2 *ND0, *ND1;
    float *h1, *part;
    int* prog;
    cudaGetSymbolAddress((void**)&ND0,  g_ND0);
    cudaGetSymbolAddress((void**)&ND1,  g_ND1);
    cudaGetSymbolAddress((void**)&h1,   g_h1);
    cudaGetSymbolAddress((void**)&part, g_part);
    cudaGetSymbolAddress((void**)&prog, g_prog);

    const int SENS_SMEM = (3 * 128 * PADW + 16 * Hn) * 4;            // 210944 B
    const int PIPE_SMEM = (128 * PADW + 256 + 2048 + 1024
                           + 2 * 128 * PADW) * 4;                    // 216064 B
    const int GEMM_SMEM = (128 * 66 + 32 * 128) * 4;                 // 50176 B
    cudaFuncSetAttribute(sensory_kernel, cudaFuncAttributeMaxDynamicSharedMemorySize, SENS_SMEM);
    cudaFuncSetAttribute(pipe_kernel,    cudaFuncAttributeMaxDynamicSharedMemorySize, PIPE_SMEM);
    cudaFuncSetAttribute(heads_kernel,   cudaFuncAttributeMaxDynamicSharedMemorySize, GEMM_SMEM);

    init_kernel<<<1, Bn>>>(prog);
    // layer-0 sensory from x [B,T,F]: u[t][b][i] -> stride_t=F, stride_b=T*F
    sensory_kernel<<<512, 256, SENS_SMEM>>>(x, Fn, Tn * Fn,
                                            s_sig, s_mu, s_w, s_ev, ND0);
    // pipelined dual-layer recurrence (layer-1 sensory params offset by H*H)
    pipe_kernel<<<128, 512, PIPE_SMEM>>>(sigma, mu_syn, w, erev, gleak, vleak, cmv,
                                         s_sig + Hn * Hn, s_mu + Hn * Hn,
                                         s_w + Hn * Hn, s_ev + Hn * Hn,
                                         ND0, ND1, h1, prog);
    // heads
    heads_kernel<<<dim3(16, 2, 16), 128, GEMM_SMEM>>>(h1, mu_w, ls_w, part);
    epilogue_kernel<<<(2 * Bn * LATn) / 256, 256>>>(part, mu_b, ls_b, out);
}